// round 9
// baseline (speedup 1.0000x reference)
#include <cuda_runtime.h>
#include <cstdint>

// Chebyshev-KAN: out[b] = sum_d sum_{k=0..8} coeff[d*9+k] * T_k(x[b,d])
// x: (16384, 512) f32; coeff: (4608,) f32; out: (16384,) f32.
//
// R9: R7's proven-fast main loop (TILE=4 row groups, <=64 regs, 4 CTAs/SM,
// warp = 64-dim slice with monomial coeffs in 9 packed-f32x2 regs, register
// double buffering, 9-shuffle fold tree) with a REDG epilogue: lane 0/8/16/24
// fire red.global.add.f32 straight into out[] (pre-zeroed by a tiny kernel).
// No scratch round-trip, no reduce kernel, no syncthreads.

#define DIM      512
#define NDEG     9
#define THREADS  256
#define TILE     4
#define NGROUPS  4096          // 16384 / 4
#define GRID1    592           // 148 SMs x 4 CTAs
#define NROWS    16384

typedef unsigned long long ull;

__device__ __forceinline__ ull pack2(float lo, float hi) {
    ull r; asm("mov.b64 %0, {%1, %2};" : "=l"(r) : "f"(lo), "f"(hi)); return r;
}
__device__ __forceinline__ void unpack2(ull v, float& lo, float& hi) {
    asm("mov.b64 {%0, %1}, %2;" : "=f"(lo), "=f"(hi) : "l"(v));
}
__device__ __forceinline__ ull fma2(ull a, ull b, ull c) {
    ull r; asm("fma.rn.f32x2 %0, %1, %2, %3;" : "=l"(r) : "l"(a), "l"(b), "l"(c)); return r;
}

// Chebyshev coeffs c[0..8] -> monomial coeffs a[0..8].
__device__ __forceinline__ void cheb2mono(const float* __restrict__ c, float* a) {
    a[8] = 128.0f * c[8];
    a[7] =  64.0f * c[7];
    a[6] = fmaf(-256.0f, c[8], 32.0f * c[6]);
    a[5] = fmaf(-112.0f, c[7], 16.0f * c[5]);
    a[4] = fmaf(160.0f, c[8], fmaf(-48.0f, c[6], 8.0f * c[4]));
    a[3] = fmaf( 56.0f, c[7], fmaf(-20.0f, c[5], 4.0f * c[3]));
    a[2] = fmaf(-32.0f, c[8], fmaf(18.0f, c[6], fmaf(-8.0f, c[4], 2.0f * c[2])));
    a[1] = fmaf( -7.0f, c[7], fmaf( 5.0f, c[5], fmaf(-3.0f, c[3], c[1])));
    a[0] = ((c[0] - c[2]) + (c[4] - c[6])) + c[8];
}

__device__ __forceinline__ void load_group(const float2* __restrict__ x2,
                                           int g, int col2, float2* xb) {
    const float2* p = x2 + (size_t)(TILE * g) * (DIM / 2) + col2;
    #pragma unroll
    for (int r = 0; r < TILE; ++r)
        xb[r] = p[r * (DIM / 2)];
}

// Compute 4 rows of this warp's 64-dim slice, fold, REDG into out[4g..4g+4).
__device__ __forceinline__ void do_group(const float2* xb, const ull* A,
                                         float* __restrict__ out,
                                         int g, int lane) {
    float acc[TILE];
    #pragma unroll
    for (int r = 0; r < TILE; ++r) {
        ull xp = pack2(xb[r].x, xb[r].y);
        ull p = A[8];
        #pragma unroll
        for (int k = 7; k >= 0; --k) p = fma2(p, xp, A[k]);
        float lo, hi; unpack2(p, lo, hi);
        acc[r] = lo + hi;
    }
    // fold tree: 9 shuffles reduce 4 rows; lane bits (4,3) -> row
    float v0, v1;
    {
        float lo = acc[0] + __shfl_xor_sync(0xffffffffu, acc[0], 16);
        float hi = acc[1] + __shfl_xor_sync(0xffffffffu, acc[1], 16);
        v0 = (lane & 16) ? hi : lo;
        lo = acc[2] + __shfl_xor_sync(0xffffffffu, acc[2], 16);
        hi = acc[3] + __shfl_xor_sync(0xffffffffu, acc[3], 16);
        v1 = (lane & 16) ? hi : lo;
    }
    float u;
    {
        float lo = v0 + __shfl_xor_sync(0xffffffffu, v0, 8);
        float hi = v1 + __shfl_xor_sync(0xffffffffu, v1, 8);
        u = (lane & 8) ? hi : lo;
    }
    u += __shfl_xor_sync(0xffffffffu, u, 4);
    u += __shfl_xor_sync(0xffffffffu, u, 2);
    u += __shfl_xor_sync(0xffffffffu, u, 1);
    // lane 0 -> row 0, lane 8 -> row 2, lane 16 -> row 1, lane 24 -> row 3
    if ((lane & 7) == 0) {
        int rm = 2 * ((lane >> 3) & 1) + ((lane >> 4) & 1);
        atomicAdd(&out[TILE * g + rm], u);   // RED.E.ADD.F32 (no return value used)
    }
}

__global__ __launch_bounds__(THREADS, 4)
void kan_cheb_partial(const float* __restrict__ x,
                      const float* __restrict__ coeff,
                      float* __restrict__ out)
{
    const int tid  = threadIdx.x;
    const int lane = tid & 31;
    const int s    = tid >> 5;            // slice 0..7 (fixed per warp)
    const int d0   = s * 64 + lane * 2;
    const int col2 = d0 >> 1;

    const float2* x2 = reinterpret_cast<const float2*>(x);

    // issue first x loads BEFORE coefficient work (independent)
    int g = blockIdx.x;
    float2 xa[TILE], xb[TILE];
    load_group(x2, g, col2, xa);

    // coeff prologue: 18 consecutive floats -> monomial -> packed regs
    float cf[18];
    {
        const float2* c2 = reinterpret_cast<const float2*>(coeff + d0 * NDEG);
        #pragma unroll
        for (int i = 0; i < 9; ++i) { float2 v = c2[i]; cf[2*i] = v.x; cf[2*i+1] = v.y; }
    }
    ull A[9];
    {
        float t0[9], t1[9];
        cheb2mono(cf, t0); cheb2mono(cf + 9, t1);
        #pragma unroll
        for (int k = 0; k < 9; ++k) A[k] = pack2(t0[k], t1[k]);
    }

    // warp-autonomous grid-stride loop, register double buffer
    for (;;) {
        int gn = g + GRID1;
        if (gn < NGROUPS) load_group(x2, gn, col2, xb);
        do_group(xa, A, out, g, lane);
        if (gn >= NGROUPS) break;
        g = gn;

        gn = g + GRID1;
        if (gn < NGROUPS) load_group(x2, gn, col2, xa);
        do_group(xb, A, out, g, lane);
        if (gn >= NGROUPS) break;
        g = gn;
    }
}

__global__ __launch_bounds__(256)
void kan_zero_out(float4* __restrict__ out4)
{
    out4[blockIdx.x * 256 + threadIdx.x] = make_float4(0.f, 0.f, 0.f, 0.f);
}

extern "C" void kernel_launch(void* const* d_in, const int* in_sizes, int n_in,
                              void* d_out, int out_size)
{
    const float* x     = (const float*)d_in[0];
    const float* coeff = (const float*)d_in[1];
    // d_in[2] = degree (int32, fixed at 8) — baked in at compile time.
    float* out = (float*)d_out;

    kan_zero_out<<<NROWS / 4 / 256, 256>>>((float4*)out);
    kan_cheb_partial<<<GRID1, THREADS>>>(x, coeff, out);
}

// round 10
// speedup vs baseline: 1.0175x; 1.0175x over previous
#include <cuda_runtime.h>
#include <cstdint>

// Chebyshev-KAN: out[b] = sum_d sum_{k=0..8} coeff[d*9+k] * T_k(x[b,d])
// x: (16384, 512) f32; coeff: (4608,) f32; out: (16384,) f32.
//
// R10: k1 = R7's warp-autonomous loop (warp = 64-dim slice, monomial coeffs
// in 9 packed-f32x2 regs, TILE=4 row groups, fold tree, STG to scratch) but
// with a DEPTH-3 register pipeline: loads for group g+2*GRID issue while
// computing group g, so 8 LDG.64 per warp stay in flight continuously
// (Little's law: ~32-64KB/SM >> 11.5KB needed for full DRAM BW).
// k2 = reduce with transposed scratch [row][8]: one thread per row, two
// coalesced LDG.128, grid 128x128 covering all SMs.

#define DIM      512
#define NDEG     9
#define THREADS  256
#define TILE     4
#define NGROUPS  4096          // 16384 / 4
#define GRID1    592           // 148 SMs x 4 CTAs
#define NROWS    16384

typedef unsigned long long ull;

__device__ __align__(16) float g_partial[NROWS][8];   // 512 KB scratch

__device__ __forceinline__ ull pack2(float lo, float hi) {
    ull r; asm("mov.b64 %0, {%1, %2};" : "=l"(r) : "f"(lo), "f"(hi)); return r;
}
__device__ __forceinline__ void unpack2(ull v, float& lo, float& hi) {
    asm("mov.b64 {%0, %1}, %2;" : "=f"(lo), "=f"(hi) : "l"(v));
}
__device__ __forceinline__ ull fma2(ull a, ull b, ull c) {
    ull r; asm("fma.rn.f32x2 %0, %1, %2, %3;" : "=l"(r) : "l"(a), "l"(b), "l"(c)); return r;
}

// Chebyshev coeffs c[0..8] -> monomial coeffs a[0..8].
__device__ __forceinline__ void cheb2mono(const float* __restrict__ c, float* a) {
    a[8] = 128.0f * c[8];
    a[7] =  64.0f * c[7];
    a[6] = fmaf(-256.0f, c[8], 32.0f * c[6]);
    a[5] = fmaf(-112.0f, c[7], 16.0f * c[5]);
    a[4] = fmaf(160.0f, c[8], fmaf(-48.0f, c[6], 8.0f * c[4]));
    a[3] = fmaf( 56.0f, c[7], fmaf(-20.0f, c[5], 4.0f * c[3]));
    a[2] = fmaf(-32.0f, c[8], fmaf(18.0f, c[6], fmaf(-8.0f, c[4], 2.0f * c[2])));
    a[1] = fmaf( -7.0f, c[7], fmaf( 5.0f, c[5], fmaf(-3.0f, c[3], c[1])));
    a[0] = ((c[0] - c[2]) + (c[4] - c[6])) + c[8];
}

__device__ __forceinline__ void load_group(const float2* __restrict__ x2,
                                           int g, int col2, float2* xb) {
    const float2* p = x2 + (size_t)(TILE * g) * (DIM / 2) + col2;
    #pragma unroll
    for (int r = 0; r < TILE; ++r)
        xb[r] = p[r * (DIM / 2)];
}

// Compute 4 rows of this warp's slice s, fold, STG into g_partial[4g+rm][s].
__device__ __forceinline__ void do_group(const float2* xb, const ull* A,
                                         int s, int g, int lane) {
    float acc[TILE];
    #pragma unroll
    for (int r = 0; r < TILE; ++r) {
        ull xp = pack2(xb[r].x, xb[r].y);
        ull p = A[8];
        #pragma unroll
        for (int k = 7; k >= 0; --k) p = fma2(p, xp, A[k]);
        float lo, hi; unpack2(p, lo, hi);
        acc[r] = lo + hi;
    }
    // fold tree: 9 shuffles reduce 4 rows; lane bits (4,3) -> row
    float v0, v1;
    {
        float lo = acc[0] + __shfl_xor_sync(0xffffffffu, acc[0], 16);
        float hi = acc[1] + __shfl_xor_sync(0xffffffffu, acc[1], 16);
        v0 = (lane & 16) ? hi : lo;
        lo = acc[2] + __shfl_xor_sync(0xffffffffu, acc[2], 16);
        hi = acc[3] + __shfl_xor_sync(0xffffffffu, acc[3], 16);
        v1 = (lane & 16) ? hi : lo;
    }
    float u;
    {
        float lo = v0 + __shfl_xor_sync(0xffffffffu, v0, 8);
        float hi = v1 + __shfl_xor_sync(0xffffffffu, v1, 8);
        u = (lane & 8) ? hi : lo;
    }
    u += __shfl_xor_sync(0xffffffffu, u, 4);
    u += __shfl_xor_sync(0xffffffffu, u, 2);
    u += __shfl_xor_sync(0xffffffffu, u, 1);
    // lane 0 -> row 0, lane 8 -> row 2, lane 16 -> row 1, lane 24 -> row 3
    if ((lane & 7) == 0) {
        int rm = 2 * ((lane >> 3) & 1) + ((lane >> 4) & 1);
        g_partial[TILE * g + rm][s] = u;
    }
}

__global__ __launch_bounds__(THREADS, 4)
void kan_cheb_partial(const float* __restrict__ x,
                      const float* __restrict__ coeff)
{
    const int tid  = threadIdx.x;
    const int lane = tid & 31;
    const int s    = tid >> 5;            // slice 0..7 (fixed per warp)
    const int d0   = s * 64 + lane * 2;
    const int col2 = d0 >> 1;

    const float2* x2 = reinterpret_cast<const float2*>(x);

    // issue first two groups' loads BEFORE coefficient work (independent)
    int g = blockIdx.x;
    float2 xa[TILE], xb[TILE], xc[TILE];
    load_group(x2, g, col2, xa);
    if (g + GRID1 < NGROUPS) load_group(x2, g + GRID1, col2, xb);

    // coeff prologue: 18 consecutive floats -> monomial -> packed regs
    float cf[18];
    {
        const float2* c2 = reinterpret_cast<const float2*>(coeff + d0 * NDEG);
        #pragma unroll
        for (int i = 0; i < 9; ++i) { float2 v = c2[i]; cf[2*i] = v.x; cf[2*i+1] = v.y; }
    }
    ull A[9];
    {
        float t0[9], t1[9];
        cheb2mono(cf, t0); cheb2mono(cf + 9, t1);
        #pragma unroll
        for (int k = 0; k < 9; ++k) A[k] = pack2(t0[k], t1[k]);
    }

    // warp-autonomous grid-stride loop, depth-3 register pipeline
    for (;;) {
        int gp = g + 2 * GRID1;
        if (gp < NGROUPS) load_group(x2, gp, col2, xc);
        do_group(xa, A, s, g, lane);
        g += GRID1;
        if (g >= NGROUPS) break;

        gp = g + 2 * GRID1;
        if (gp < NGROUPS) load_group(x2, gp, col2, xa);
        do_group(xb, A, s, g, lane);
        g += GRID1;
        if (g >= NGROUPS) break;

        gp = g + 2 * GRID1;
        if (gp < NGROUPS) load_group(x2, gp, col2, xb);
        do_group(xc, A, s, g, lane);
        g += GRID1;
        if (g >= NGROUPS) break;
    }
}

// One thread per row: 8 contiguous partials via 2x LDG.128, sum, store.
__global__ __launch_bounds__(128)
void kan_cheb_reduce(float* __restrict__ out)
{
    const int row = blockIdx.x * 128 + threadIdx.x;
    const float4* p = reinterpret_cast<const float4*>(g_partial[row]);
    float4 a = p[0], b = p[1];
    out[row] = ((a.x + a.y) + (a.z + a.w)) + ((b.x + b.y) + (b.z + b.w));
}

extern "C" void kernel_launch(void* const* d_in, const int* in_sizes, int n_in,
                              void* d_out, int out_size)
{
    const float* x     = (const float*)d_in[0];
    const float* coeff = (const float*)d_in[1];
    // d_in[2] = degree (int32, fixed at 8) — baked in at compile time.
    float* out = (float*)d_out;

    kan_cheb_partial<<<GRID1, THREADS>>>(x, coeff);
    kan_cheb_reduce<<<NROWS / 128, 128>>>(out);
}

// round 11
// speedup vs baseline: 1.2113x; 1.1905x over previous
#include <cuda_runtime.h>
#include <cstdint>

// Chebyshev-KAN: out[b] = sum_d sum_{k=0..8} coeff[d*9+k] * T_k(x[b,d])
// x: (16384, 512) f32; coeff: (4608,) f32; out: (16384,) f32.
//
// R11: single kernel. R10's depth-3-pipelined warp-autonomous engine
// (warp = 64-dim slice, monomial coeffs in 9 packed-f32x2 regs, TILE=4 row
// groups, 9-shuffle fold tree) but with CONTIGUOUS chunk assignment:
// CTA i owns <=7 consecutive groups (<=28 rows). Per-group partials go to
// a tiny smem array (warp writes its own column, no sync), and one final
// __syncthreads + 28-thread sum writes out[] directly. No scratch buffer,
// no second kernel (trailing kernels measured ~4.2us of pure overhead).

#define DIM      512
#define NDEG     9
#define THREADS  256
#define TILE     4
#define NGROUPS  4096          // 16384 / 4
#define GRID1    592           // 148 SMs x 4 CTAs, single wave
#define CHUNK_BIG 544          // 4096 = 592*6 + 544 -> first 544 CTAs get 7
#define MAXG     7
#define SSTRIDE  9             // smem row stride (floats), conflict-dodging

typedef unsigned long long ull;

__device__ __forceinline__ ull pack2(float lo, float hi) {
    ull r; asm("mov.b64 %0, {%1, %2};" : "=l"(r) : "f"(lo), "f"(hi)); return r;
}
__device__ __forceinline__ void unpack2(ull v, float& lo, float& hi) {
    asm("mov.b64 {%0, %1}, %2;" : "=f"(lo), "=f"(hi) : "l"(v));
}
__device__ __forceinline__ ull fma2(ull a, ull b, ull c) {
    ull r; asm("fma.rn.f32x2 %0, %1, %2, %3;" : "=l"(r) : "l"(a), "l"(b), "l"(c)); return r;
}

// Chebyshev coeffs c[0..8] -> monomial coeffs a[0..8].
__device__ __forceinline__ void cheb2mono(const float* __restrict__ c, float* a) {
    a[8] = 128.0f * c[8];
    a[7] =  64.0f * c[7];
    a[6] = fmaf(-256.0f, c[8], 32.0f * c[6]);
    a[5] = fmaf(-112.0f, c[7], 16.0f * c[5]);
    a[4] = fmaf(160.0f, c[8], fmaf(-48.0f, c[6], 8.0f * c[4]));
    a[3] = fmaf( 56.0f, c[7], fmaf(-20.0f, c[5], 4.0f * c[3]));
    a[2] = fmaf(-32.0f, c[8], fmaf(18.0f, c[6], fmaf(-8.0f, c[4], 2.0f * c[2])));
    a[1] = fmaf( -7.0f, c[7], fmaf( 5.0f, c[5], fmaf(-3.0f, c[3], c[1])));
    a[0] = ((c[0] - c[2]) + (c[4] - c[6])) + c[8];
}

__device__ __forceinline__ void load_group(const float2* __restrict__ x2,
                                           int g, int col2, float2* xb) {
    const float2* p = x2 + (size_t)(TILE * g) * (DIM / 2) + col2;
    #pragma unroll
    for (int r = 0; r < TILE; ++r)
        xb[r] = p[r * (DIM / 2)];
}

// Compute 4 rows of this warp's slice s, fold, store into smem partials.
__device__ __forceinline__ void do_group(const float2* xb, const ull* A,
                                         float* __restrict__ s_part,
                                         int s, int lrow0, int lane) {
    float acc[TILE];
    #pragma unroll
    for (int r = 0; r < TILE; ++r) {
        ull xp = pack2(xb[r].x, xb[r].y);
        ull p = A[8];
        #pragma unroll
        for (int k = 7; k >= 0; --k) p = fma2(p, xp, A[k]);
        float lo, hi; unpack2(p, lo, hi);
        acc[r] = lo + hi;
    }
    // fold tree: 9 shuffles reduce 4 rows; lane bits (4,3) -> row
    float v0, v1;
    {
        float lo = acc[0] + __shfl_xor_sync(0xffffffffu, acc[0], 16);
        float hi = acc[1] + __shfl_xor_sync(0xffffffffu, acc[1], 16);
        v0 = (lane & 16) ? hi : lo;
        lo = acc[2] + __shfl_xor_sync(0xffffffffu, acc[2], 16);
        hi = acc[3] + __shfl_xor_sync(0xffffffffu, acc[3], 16);
        v1 = (lane & 16) ? hi : lo;
    }
    float u;
    {
        float lo = v0 + __shfl_xor_sync(0xffffffffu, v0, 8);
        float hi = v1 + __shfl_xor_sync(0xffffffffu, v1, 8);
        u = (lane & 8) ? hi : lo;
    }
    u += __shfl_xor_sync(0xffffffffu, u, 4);
    u += __shfl_xor_sync(0xffffffffu, u, 2);
    u += __shfl_xor_sync(0xffffffffu, u, 1);
    // lane 0 -> row 0, lane 8 -> row 2, lane 16 -> row 1, lane 24 -> row 3
    if ((lane & 7) == 0) {
        int rm = 2 * ((lane >> 3) & 1) + ((lane >> 4) & 1);
        s_part[(lrow0 + rm) * SSTRIDE + s] = u;
    }
}

__global__ __launch_bounds__(THREADS, 4)
void kan_cheb_kernel(const float* __restrict__ x,
                     const float* __restrict__ coeff,
                     float* __restrict__ out)
{
    __shared__ float s_part[MAXG * TILE * SSTRIDE];   // 7*4*9*4 = 1008 B

    const int tid  = threadIdx.x;
    const int lane = tid & 31;
    const int s    = tid >> 5;            // slice 0..7 (fixed per warp)
    const int d0   = s * 64 + lane * 2;
    const int col2 = d0 >> 1;

    // contiguous chunk: first CHUNK_BIG CTAs get 7 groups, rest get 6
    const int bid  = blockIdx.x;
    const int big  = (bid < CHUNK_BIG);
    const int g0   = big ? (bid * 7) : (CHUNK_BIG * 7 + (bid - CHUNK_BIG) * 6);
    const int gend = g0 + (big ? 7 : 6);

    const float2* x2 = reinterpret_cast<const float2*>(x);

    // issue first two groups' loads BEFORE coefficient work (independent)
    int g = g0;
    float2 xa[TILE], xb[TILE], xc[TILE];
    load_group(x2, g, col2, xa);
    if (g + 1 < gend) load_group(x2, g + 1, col2, xb);

    // coeff prologue: 18 consecutive floats -> monomial -> packed regs
    float cf[18];
    {
        const float2* c2 = reinterpret_cast<const float2*>(coeff + d0 * NDEG);
        #pragma unroll
        for (int i = 0; i < 9; ++i) { float2 v = c2[i]; cf[2*i] = v.x; cf[2*i+1] = v.y; }
    }
    ull A[9];
    {
        float t0[9], t1[9];
        cheb2mono(cf, t0); cheb2mono(cf + 9, t1);
        #pragma unroll
        for (int k = 0; k < 9; ++k) A[k] = pack2(t0[k], t1[k]);
    }

    // depth-3 register pipeline over the CTA's contiguous groups
    for (;;) {
        if (g + 2 < gend) load_group(x2, g + 2, col2, xc);
        do_group(xa, A, s_part, s, (g - g0) * TILE, lane);
        if (++g >= gend) break;

        if (g + 2 < gend) load_group(x2, g + 2, col2, xa);
        do_group(xb, A, s_part, s, (g - g0) * TILE, lane);
        if (++g >= gend) break;

        if (g + 2 < gend) load_group(x2, g + 2, col2, xb);
        do_group(xc, A, s_part, s, (g - g0) * TILE, lane);
        if (++g >= gend) break;
    }

    // in-CTA finalize: one sync, then one thread per row sums 8 partials
    __syncthreads();
    const int nrows = (gend - g0) * TILE;
    if (tid < nrows) {
        const float* p = &s_part[tid * SSTRIDE];
        float r = ((p[0] + p[1]) + (p[2] + p[3])) + ((p[4] + p[5]) + (p[6] + p[7]));
        out[g0 * TILE + tid] = r;
    }
}

extern "C" void kernel_launch(void* const* d_in, const int* in_sizes, int n_in,
                              void* d_out, int out_size)
{
    const float* x     = (const float*)d_in[0];
    const float* coeff = (const float*)d_in[1];
    // d_in[2] = degree (int32, fixed at 8) — baked in at compile time.
    float* out = (float*)d_out;

    kan_cheb_kernel<<<GRID1, THREADS>>>(x, coeff, out);
}

// round 12
// speedup vs baseline: 1.2149x; 1.0030x over previous
#include <cuda_runtime.h>
#include <cstdint>

// Chebyshev-KAN: out[b] = sum_d sum_{k=0..8} coeff[d*9+k] * T_k(x[b,d])
// x: (16384, 512) f32; coeff: (4608,) f32; out: (16384,) f32.
//
// R12: A/B vs R11 — identical fused engine (warp = 64-dim slice, monomial
// coeffs in 9 packed-f32x2 regs, TILE=4 row groups, depth-3 register
// pipeline, 9-shuffle fold tree, smem partials + single __syncthreads,
// direct out[] stores), but GRID-STRIDE group assignment (g = bid + it*592,
// like R10's fast main loop) instead of contiguous chunks. smem partial
// slot = iteration index; epilogue scatters <=28 scalar stores per CTA.

#define DIM      512
#define NDEG     9
#define THREADS  256
#define TILE     4
#define NGROUPS  4096          // 16384 / 4
#define GRID1    592           // 148 SMs x 4 CTAs, single wave
#define MAXIT    7             // ceil(4096/592)
#define SSTRIDE  9             // smem row stride (floats), conflict-dodging

typedef unsigned long long ull;

__device__ __forceinline__ ull pack2(float lo, float hi) {
    ull r; asm("mov.b64 %0, {%1, %2};" : "=l"(r) : "f"(lo), "f"(hi)); return r;
}
__device__ __forceinline__ void unpack2(ull v, float& lo, float& hi) {
    asm("mov.b64 {%0, %1}, %2;" : "=f"(lo), "=f"(hi) : "l"(v));
}
__device__ __forceinline__ ull fma2(ull a, ull b, ull c) {
    ull r; asm("fma.rn.f32x2 %0, %1, %2, %3;" : "=l"(r) : "l"(a), "l"(b), "l"(c)); return r;
}

// Chebyshev coeffs c[0..8] -> monomial coeffs a[0..8].
__device__ __forceinline__ void cheb2mono(const float* __restrict__ c, float* a) {
    a[8] = 128.0f * c[8];
    a[7] =  64.0f * c[7];
    a[6] = fmaf(-256.0f, c[8], 32.0f * c[6]);
    a[5] = fmaf(-112.0f, c[7], 16.0f * c[5]);
    a[4] = fmaf(160.0f, c[8], fmaf(-48.0f, c[6], 8.0f * c[4]));
    a[3] = fmaf( 56.0f, c[7], fmaf(-20.0f, c[5], 4.0f * c[3]));
    a[2] = fmaf(-32.0f, c[8], fmaf(18.0f, c[6], fmaf(-8.0f, c[4], 2.0f * c[2])));
    a[1] = fmaf( -7.0f, c[7], fmaf( 5.0f, c[5], fmaf(-3.0f, c[3], c[1])));
    a[0] = ((c[0] - c[2]) + (c[4] - c[6])) + c[8];
}

__device__ __forceinline__ void load_group(const float2* __restrict__ x2,
                                           int g, int col2, float2* xb) {
    const float2* p = x2 + (size_t)(TILE * g) * (DIM / 2) + col2;
    #pragma unroll
    for (int r = 0; r < TILE; ++r)
        xb[r] = p[r * (DIM / 2)];
}

// Compute 4 rows of this warp's slice s, fold, store into smem slot.
__device__ __forceinline__ void do_group(const float2* xb, const ull* A,
                                         float* __restrict__ s_part,
                                         int s, int slot, int lane) {
    float acc[TILE];
    #pragma unroll
    for (int r = 0; r < TILE; ++r) {
        ull xp = pack2(xb[r].x, xb[r].y);
        ull p = A[8];
        #pragma unroll
        for (int k = 7; k >= 0; --k) p = fma2(p, xp, A[k]);
        float lo, hi; unpack2(p, lo, hi);
        acc[r] = lo + hi;
    }
    // fold tree: 9 shuffles reduce 4 rows; lane bits (4,3) -> row
    float v0, v1;
    {
        float lo = acc[0] + __shfl_xor_sync(0xffffffffu, acc[0], 16);
        float hi = acc[1] + __shfl_xor_sync(0xffffffffu, acc[1], 16);
        v0 = (lane & 16) ? hi : lo;
        lo = acc[2] + __shfl_xor_sync(0xffffffffu, acc[2], 16);
        hi = acc[3] + __shfl_xor_sync(0xffffffffu, acc[3], 16);
        v1 = (lane & 16) ? hi : lo;
    }
    float u;
    {
        float lo = v0 + __shfl_xor_sync(0xffffffffu, v0, 8);
        float hi = v1 + __shfl_xor_sync(0xffffffffu, v1, 8);
        u = (lane & 8) ? hi : lo;
    }
    u += __shfl_xor_sync(0xffffffffu, u, 4);
    u += __shfl_xor_sync(0xffffffffu, u, 2);
    u += __shfl_xor_sync(0xffffffffu, u, 1);
    // lane 0 -> row 0, lane 8 -> row 2, lane 16 -> row 1, lane 24 -> row 3
    if ((lane & 7) == 0) {
        int rm = 2 * ((lane >> 3) & 1) + ((lane >> 4) & 1);
        s_part[(slot * TILE + rm) * SSTRIDE + s] = u;
    }
}

__global__ __launch_bounds__(THREADS, 4)
void kan_cheb_kernel(const float* __restrict__ x,
                     const float* __restrict__ coeff,
                     float* __restrict__ out)
{
    __shared__ float s_part[MAXIT * TILE * SSTRIDE];   // 7*4*9*4 = 1008 B

    const int tid  = threadIdx.x;
    const int lane = tid & 31;
    const int s    = tid >> 5;            // slice 0..7 (fixed per warp)
    const int d0   = s * 64 + lane * 2;
    const int col2 = d0 >> 1;
    const int bid  = blockIdx.x;

    const float2* x2 = reinterpret_cast<const float2*>(x);

    // issue first two groups' loads BEFORE coefficient work (independent)
    int g = bid;
    float2 xa[TILE], xb[TILE], xc[TILE];
    load_group(x2, g, col2, xa);
    if (g + GRID1 < NGROUPS) load_group(x2, g + GRID1, col2, xb);

    // coeff prologue: 18 consecutive floats -> monomial -> packed regs
    float cf[18];
    {
        const float2* c2 = reinterpret_cast<const float2*>(coeff + d0 * NDEG);
        #pragma unroll
        for (int i = 0; i < 9; ++i) { float2 v = c2[i]; cf[2*i] = v.x; cf[2*i+1] = v.y; }
    }
    ull A[9];
    {
        float t0[9], t1[9];
        cheb2mono(cf, t0); cheb2mono(cf + 9, t1);
        #pragma unroll
        for (int k = 0; k < 9; ++k) A[k] = pack2(t0[k], t1[k]);
    }

    // grid-stride loop, depth-3 register pipeline, slot = iteration index
    int slot = 0;
    for (;;) {
        int gp = g + 2 * GRID1;
        if (gp < NGROUPS) load_group(x2, gp, col2, xc);
        do_group(xa, A, s_part, s, slot, lane);
        g += GRID1; ++slot;
        if (g >= NGROUPS) break;

        gp = g + 2 * GRID1;
        if (gp < NGROUPS) load_group(x2, gp, col2, xa);
        do_group(xb, A, s_part, s, slot, lane);
        g += GRID1; ++slot;
        if (g >= NGROUPS) break;

        gp = g + 2 * GRID1;
        if (gp < NGROUPS) load_group(x2, gp, col2, xb);
        do_group(xc, A, s_part, s, slot, lane);
        g += GRID1; ++slot;
        if (g >= NGROUPS) break;
    }

    // in-CTA finalize: one sync; thread (slot,rm) sums 8 partials, scatters
    __syncthreads();
    if (tid < MAXIT * TILE) {
        const int it = tid >> 2;
        const int rm = tid & 3;
        const int gg = bid + it * GRID1;
        if (gg < NGROUPS) {
            const float* p = &s_part[tid * SSTRIDE];
            float r = ((p[0] + p[1]) + (p[2] + p[3])) + ((p[4] + p[5]) + (p[6] + p[7]));
            out[gg * TILE + rm] = r;
        }
    }
}

extern "C" void kernel_launch(void* const* d_in, const int* in_sizes, int n_in,
                              void* d_out, int out_size)
{
    const float* x     = (const float*)d_in[0];
    const float* coeff = (const float*)d_in[1];
    // d_in[2] = degree (int32, fixed at 8) — baked in at compile time.
    float* out = (float*)d_out;

    kan_cheb_kernel<<<GRID1, THREADS>>>(x, coeff, out);
}